// round 17
// baseline (speedup 1.0000x reference)
#include <cuda_runtime.h>
#include <math_constants.h>

// Roi_61564061221098 round 17: R16 + w-direction pair tables.
//  transpose: x -> level-0 NHWC table.
//  build_level kh=1..3: T[kh][h] = max(T[kh-1][h], T[kh-1][h+2^(kh-1)]).
//  build_w   kh=0..3: Tw[kh][h][w] = max(T[kh][h][w], T[kh][h][w+1]).
//  roi_pool:  per bin, read 2 table rows; w covered by ceil(s/2) PAIR lookups
//             (tail clamped to we-2; overlap exact since max is idempotent).
//             s==1 bins read the base table. Bit-exact.

#define NC    512
#define NC4   (NC / 4)
#define FH    50
#define FW    68
#define NPOS  (FH * FW)          // 3400
#define PP    7
#define SCALE 0.0625f
#define NEG_INF (-CUDART_INF_F)
#define SSTR  517                // sbin row stride (coprime with 32 banks)
#define NB0   28                 // bins in half 0 (ph 0..3)
#define NB1   21                 // bins in half 1 (ph 4..6)
#define SMEMB (NB0 * SSTR * 4)   // 57,904 B
#define LEVS  (4 * NPOS * NC4)   // float4 per level (4 images)

__device__ float4 g_tab [4 * LEVS];   // h-levels kh=0..3
__device__ float4 g_tabw[4 * LEVS];   // w-pair table per kh level
// per-roi record: [0]=n, [1..7]=hs|he<<8|h2<<16|k<<24, [8..14]=ws<<16|we<<24
__device__ __align__(16) int g_rec[4096 * 16];

__global__ void transpose_kernel(const float* __restrict__ x)
{
    __shared__ float tile[32][33];
    const int n  = blockIdx.z;
    const int c0 = blockIdx.y * 32;
    const int p0 = blockIdx.x * 32;
    const int tx = threadIdx.x, ty = threadIdx.y;    // block (32, 8)
    float* __restrict__ dst = (float*)g_tab;         // level 0

#pragma unroll
    for (int dy = 0; dy < 32; dy += 8) {
        const int c = c0 + ty + dy;
        const int p = p0 + tx;
        tile[ty + dy][tx] = (p < NPOS) ? x[(n * NC + c) * NPOS + p] : 0.0f;
    }
    __syncthreads();
#pragma unroll
    for (int dy = 0; dy < 32; dy += 8) {
        const int p = p0 + ty + dy;
        if (p < NPOS) dst[((size_t)n * NPOS + p) * NC + c0 + tx] = tile[tx][ty + dy];
    }
}

__device__ __forceinline__ void fmax4(float4& a, const float4 b)
{
    a.x = fmaxf(a.x, b.x); a.y = fmaxf(a.y, b.y);
    a.z = fmaxf(a.z, b.z); a.w = fmaxf(a.w, b.w);
}

__global__ void build_level(int k, int rows)
{
    const int idx = blockIdx.x * 256 + threadIdx.x;
    const int total = 4 * rows * FW * NC4;
    if (idx >= total) return;
    const int c  = idx & (NC4 - 1);
    const int rp = idx >> 7;             // NC4 = 128
    const int w  = rp % FW;
    const int t  = rp / FW;
    const int h  = t % rows;
    const int n  = t / rows;

    const int half = 1 << (k - 1);
    const float4* src = g_tab + (size_t)(k - 1) * LEVS
                        + ((size_t)n * NPOS + h * FW + w) * NC4 + c;
    float4 a = src[0];
    fmax4(a, src[(size_t)half * FW * NC4]);
    g_tab[(size_t)k * LEVS + ((size_t)n * NPOS + h * FW + w) * NC4 + c] = a;
}

__global__ void build_w(int kh, int rows)
{
    const int idx = blockIdx.x * 256 + threadIdx.x;
    const int total = 4 * rows * (FW - 1) * NC4;
    if (idx >= total) return;
    const int c  = idx & (NC4 - 1);
    const int rp = idx >> 7;
    const int w  = rp % (FW - 1);
    const int t  = rp / (FW - 1);
    const int h  = t % rows;
    const int n  = t / rows;

    const size_t off = ((size_t)n * NPOS + h * FW + w) * NC4 + c;
    const float4* src = g_tab + (size_t)kh * LEVS + off;
    float4 a = src[0];
    fmax4(a, src[NC4]);                  // neighbor column w+1
    g_tabw[(size_t)kh * LEVS + off] = a;
}

__global__ void roi_prep(const float* __restrict__ rois,
                         const int*   __restrict__ ridx, int R)
{
    int r = blockIdx.x * blockDim.x + threadIdx.x;
    if (r >= R) return;

    const float y1 = rois[r * 4 + 0];
    const float x1 = rois[r * 4 + 1];
    const float y2 = rois[r * 4 + 2];
    const float x2 = rois[r * 4 + 3];
    const float rb0 = rintf(__fmul_rn(x1, SCALE));
    const float rb1 = rintf(__fmul_rn(y1, SCALE));
    const float rb2 = rintf(__fmul_rn(x2, SCALE));
    const float rb3 = rintf(__fmul_rn(y2, SCALE));
    const float roiw = fmaxf(__fadd_rn(__fsub_rn(rb2, rb0), 1.0f), 1.0f);
    const float roih = fmaxf(__fadd_rn(__fsub_rn(rb3, rb1), 1.0f), 1.0f);
    const float R7 = (float)(1.0 / 7.0);          // XLA: x/7 -> x * fl(1/7)
    const float bw = __fmul_rn(roiw, R7);
    const float bh = __fmul_rn(roih, R7);

    int* rec = g_rec + r * 16;
    rec[0] = ridx[r];
#pragma unroll
    for (int p = 0; p < PP; p++) {
        const float fp  = (float)p;
        const float fp1 = (float)(p + 1);
        int hs = (int)fminf(fmaxf(__fadd_rn(floorf(__fmul_rn(fp,  bh)), rb1), 0.0f), (float)FH);
        int he = (int)fminf(fmaxf(__fadd_rn(ceilf (__fmul_rn(fp1, bh)), rb1), 0.0f), (float)FH);
        int ws = (int)fminf(fmaxf(__fadd_rn(floorf(__fmul_rn(fp,  bw)), rb0), 0.0f), (float)FW);
        int we = (int)fminf(fmaxf(__fadd_rn(ceilf (__fmul_rn(fp1, bw)), rb0), 0.0f), (float)FW);

        // sparse-table level: k = floor(log2(s-1)) for s>=2 (s<=9 -> k<=3)
        const int s = he - hs;
        int k = 0, h2 = hs;
        if (s >= 2) {
            k = 31 - __clz(s - 1);
            if (k > 3) k = 3;
            h2 = he - (1 << k);
        }
        rec[1 + p] = hs | (he << 8) | (h2 << 16) | (k << 24);
        rec[8 + p] = (ws << 16) | (we << 24);
    }
}

__global__ __launch_bounds__(256, 3)
void roi_pool(float* __restrict__ out, int R)
{
    extern __shared__ float sbin[];                 // [nb][SSTR]

    const int bid  = blockIdx.x;
    const int r    = bid >> 1;
    const int half = bid & 1;
    const int tid  = threadIdx.x;
    const int warp = tid >> 5;
    const int lane = tid & 31;
    const int chid = warp & 3;          // 128-channel slice
    const int pwg  = warp >> 2;         // 0: pw 0-3, 1: pw 4-6

    int v = 0;
    if (lane < 16) v = g_rec[r * 16 + lane];
    const int n = __shfl_sync(0xffffffffu, v, 0);

    const int npw = pwg ? 3 : 4;
    const int pw0 = pwg * 4;
    int wsA[4], weA[4];
#pragma unroll
    for (int i = 0; i < 4; i++) {
        const int qk = __shfl_sync(0xffffffffu, v, 8 + pw0 + (i < npw ? i : 0));
        wsA[i] = (qk >> 16) & 0xff;
        weA[i] = (qk >> 24) & 0xff;
        if (i >= npw) { wsA[i] = 0; weA[i] = 0; }
    }
    const int phN = half ? 3 : 4;
    const int ph0 = half ? 4 : 0;

    const size_t choff = (size_t)n * NPOS * NC4 + chid * 32 + lane;
    const float4 NI4 = make_float4(NEG_INF, NEG_INF, NEG_INF, NEG_INF);

    for (int phi = 0; phi < phN; phi++) {
        const int hk = __shfl_sync(0xffffffffu, v, 1 + ph0 + phi);
        const int hs = hk & 0xff;
        const int he = (hk >> 8) & 0xff;
        const int h2 = (hk >> 16) & 0xff;
        const int k  = (hk >> 24) & 0xff;
        const bool hnon = hs < he;

        const size_t lvl = (size_t)k * LEVS + choff;
        const float4* __restrict__ rAb = g_tab  + lvl + (size_t)hs * FW * NC4;
        const float4* __restrict__ rBb = g_tab  + lvl + (size_t)h2 * FW * NC4;
        const float4* __restrict__ rAw = g_tabw + lvl + (size_t)hs * FW * NC4;
        const float4* __restrict__ rBw = g_tabw + lvl + (size_t)h2 * FW * NC4;

#pragma unroll
        for (int i = 0; i < 4; i++) {
            if (i >= npw) break;
            const int ws = wsA[i], we = weA[i];
            const int s = we - ws;
            float4 acc = NI4;
            if (hnon && s > 0) {
                if (s == 1) {
                    const float4 a0 = rAb[(size_t)ws * NC4];
                    const float4 b0 = rBb[(size_t)ws * NC4];
                    fmax4(acc, a0); fmax4(acc, b0);
                } else {
                    // pairs at ws, ws+2, ... ; tail clamped to we-2 (overlap OK)
                    const float4* pA = rAw + (size_t)ws * NC4;
                    const float4* pB = rBw + (size_t)ws * NC4;
                    int w = ws;
                    for (; w + 4 <= we; w += 4) {     // 4 loads in flight
                        const float4 a0 = pA[0];
                        const float4 b0 = pB[0];
                        const float4 a1 = pA[2 * NC4];
                        const float4 b1 = pB[2 * NC4];
                        fmax4(acc, a0); fmax4(acc, b0);
                        fmax4(acc, a1); fmax4(acc, b1);
                        pA += 4 * NC4; pB += 4 * NC4;
                    }
                    const int rem = we - w;
                    if (rem == 3) {
                        const float4 a0 = pA[0];
                        const float4 b0 = pB[0];
                        const float4 a1 = pA[NC4];
                        const float4 b1 = pB[NC4];
                        fmax4(acc, a0); fmax4(acc, b0);
                        fmax4(acc, a1); fmax4(acc, b1);
                    } else if (rem == 2) {
                        const float4 a0 = pA[0];
                        const float4 b0 = pB[0];
                        fmax4(acc, a0); fmax4(acc, b0);
                    } else if (rem == 1) {
                        const float4 a0 = rAw[(size_t)(we - 2) * NC4];
                        const float4 b0 = rBw[(size_t)(we - 2) * NC4];
                        fmax4(acc, a0); fmax4(acc, b0);
                    }
                }
            }
            // empty bin / all -inf -> 0.0 per reference isfinite rule
            const int b = phi * PP + pw0 + i;
            float* sp = sbin + b * SSTR + chid * 128 + lane * 4;
            sp[0] = (acc.x == NEG_INF) ? 0.0f : acc.x;
            sp[1] = (acc.y == NEG_INF) ? 0.0f : acc.y;
            sp[2] = (acc.z == NEG_INF) ? 0.0f : acc.z;
            sp[3] = (acc.w == NEG_INF) ? 0.0f : acc.w;
        }
    }
    __syncthreads();

    // flush: out[r][ch][half ? 28+b : b]
    const size_t ob = (size_t)r * (NC * 49) + (half ? NB0 : 0);
    if (half == 0) {
        for (int i = tid; i < NB0 * NC; i += 256) {
            const int ch = i / NB0;
            const int b  = i - ch * NB0;
            out[ob + ch * 49 + b] = sbin[b * SSTR + ch];
        }
    } else {
        for (int i = tid; i < NB1 * NC; i += 256) {
            const int ch = i / NB1;
            const int b  = i - ch * NB1;
            out[ob + ch * 49 + b] = sbin[b * SSTR + ch];
        }
    }
}

extern "C" void kernel_launch(void* const* d_in, const int* in_sizes, int n_in,
                              void* d_out, int out_size)
{
    const float* x    = (const float*)d_in[0];
    const float* rois = (const float*)d_in[1];
    const int*   ridx = (const int*)d_in[2];
    float*       out  = (float*)d_out;
    const int R = in_sizes[2];

    cudaFuncSetAttribute(roi_pool, cudaFuncAttributeMaxDynamicSharedMemorySize,
                         SMEMB);

    dim3 tgrid((NPOS + 31) / 32, NC / 32, 4);
    transpose_kernel<<<tgrid, dim3(32, 8)>>>(x);
    for (int k = 1; k <= 3; k++) {
        const int rows  = FH - (1 << k) + 1;
        const int total = 4 * rows * FW * NC4;
        build_level<<<(total + 255) / 256, 256>>>(k, rows);
    }
    for (int kh = 0; kh <= 3; kh++) {
        const int rows  = FH - (1 << kh) + 1;
        const int total = 4 * rows * (FW - 1) * NC4;
        build_w<<<(total + 255) / 256, 256>>>(kh, rows);
    }
    roi_prep<<<(R + 255) / 256, 256>>>(rois, ridx, R);
    roi_pool<<<R * 2, 256, SMEMB>>>(out, R);
}